// round 7
// baseline (speedup 1.0000x reference)
#include <cuda_runtime.h>
#include <math.h>

// Problem dims
#define TT 256
#define BB 64
#define EE 768
#define HH 512
#define H2 1024
#define GG 2048            // 4*H
#define TB (TT*BB)         // 16384

// ---------------- scratch (device globals; no allocation allowed) ----------
__device__ float g_pre[2][(size_t)BB*TT*GG];   // [dir][b][t][g]  (bias included)
__device__ float g_h[2][2][TT*HH];             // [pingpong][dir][t*H+j]
__device__ float g_c[2][TT*HH];                // [dir][t*H+j]
__device__ float g_sents[(size_t)TB*H2];       // [t][b][h2]
__device__ float g_hW[(size_t)TB*H2];          // [t][b][k]
__device__ float g_WnovT[(size_t)H2*H2];       // W_nov transposed (K-major)
__device__ float g_docmean[BB*H2];
__device__ float g_doc[BB*H2];
__device__ float g_u[BB*H2];
__device__ float g_absp[TT];
__device__ float g_s0[BB*TT];

// =========================================================================
// mma.sync 3xTF32 GEMM machinery — in-loop split, 3-stage cp.async,
// one __syncthreads per K-chunk, warp tile 32x32.
// =========================================================================
#define LDSS 36                          // smem row stride (floats)
#define TILEA_F (128*LDSS)               // 128-row tile
#define TILEB_F (128*LDSS)
#define TILE64_F (64*LDSS)               // 64-row tile
// big GEMM: 3 stages x (A128 + B128)
#define SMEM_G (3*(TILEA_F+TILEB_F)*4)   // 110592 B
// rec: 3 stages x (A64 + B128)
#define SMEM_R (3*(TILE64_F+TILEB_F)*4)  // 82944 B

__device__ __forceinline__ void cp16(unsigned s, const float* g) {
    asm volatile("cp.async.cg.shared.global [%0], [%1], 16;"
                 :: "r"(s), "l"(__cvta_generic_to_global((void*)g)));
}
__device__ __forceinline__ void cp_commit() {
    asm volatile("cp.async.commit_group;" ::: "memory");
}
__device__ __forceinline__ void cp_wait1() {
    asm volatile("cp.async.wait_group 1;" ::: "memory");
}
__device__ __forceinline__ void cp_wait0() {
    asm volatile("cp.async.wait_group 0;" ::: "memory");
}
__device__ __forceinline__ unsigned smem_u32(const void* p) {
    unsigned a;
    asm("{ .reg .u64 t; cvta.to.shared.u64 t, %1; cvt.u32.u64 %0, t; }"
        : "=r"(a) : "l"(p));
    return a;
}
__device__ __forceinline__ void mma8(float c[4], const unsigned a[4], const unsigned b[2]) {
    asm volatile(
        "mma.sync.aligned.m16n8k8.row.col.f32.tf32.tf32.f32 "
        "{%0,%1,%2,%3}, {%4,%5,%6,%7}, {%8,%9}, {%0,%1,%2,%3};\n"
        : "+f"(c[0]), "+f"(c[1]), "+f"(c[2]), "+f"(c[3])
        : "r"(a[0]), "r"(a[1]), "r"(a[2]), "r"(a[3]), "r"(b[0]), "r"(b[1]));
}
__device__ __forceinline__ unsigned cvt_tf32(float f) {
    unsigned u;
    asm("cvt.rna.tf32.f32 %0, %1;" : "=r"(u) : "f"(f));
    return u;
}
__device__ __forceinline__ void split_tf32(float f, unsigned& hi, unsigned& lo) {
    hi = cvt_tf32(f);
    lo = cvt_tf32(f - __uint_as_float(hi));
}

// ---- loaders (K-chunk = 32 floats = 8 float4 per row) ----------------------
// 128 rows with 512 threads: 2 float4 per thread
__device__ __forceinline__ void ld128_t512(const float* __restrict__ g, int ldg,
                                           unsigned sb, int tid) {
    #pragma unroll
    for (int q = 0; q < 2; q++) {
        int idx = q * 512 + tid;
        int row = idx >> 3, c = (idx & 7) * 4;
        cp16(sb + (unsigned)((row * LDSS + c) * 4), g + (size_t)row * ldg + c);
    }
}
// 64 rows with 256 threads: 2 float4 per thread
__device__ __forceinline__ void ld64_t256(const float* __restrict__ g, int ldg,
                                          unsigned sb, int tid) {
    #pragma unroll
    for (int q = 0; q < 2; q++) {
        int idx = q * 256 + tid;
        int row = idx >> 3, c = (idx & 7) * 4;
        cp16(sb + (unsigned)((row * LDSS + c) * 4), g + (size_t)row * ldg + c);
    }
}
// 128 gate-grouped W rows with 256 threads: logical row r -> W row (r>>5)*512+j0+(r&31)
__device__ __forceinline__ void ld128gate_t256(const float* __restrict__ W, int j0,
                                               int koff, unsigned sb, int tid) {
    #pragma unroll
    for (int q = 0; q < 4; q++) {
        int idx = q * 256 + tid;
        int row = idx >> 3, c = (idx & 7) * 4;
        int grow = (row >> 5) * 512 + j0 + (row & 31);
        cp16(sb + (unsigned)((row * LDSS + c) * 4), W + (size_t)grow * HH + koff + c);
    }
}

// ---- warp-tile 32x32 compute over one 32-K chunk (in-loop split) ----------
__device__ __forceinline__ void compute_warp32(
    const float* sA, const float* sB, int mb, int nb, int lane,
    float acc[2][4][4])
{
    int g = lane >> 2, tig = lane & 3;
    #pragma unroll
    for (int kk = 0; kk < 4; kk++) {
        int k0 = kk * 8 + tig;
        unsigned ah[2][4], al[2][4], bh[4][2], bl[4][2];
        #pragma unroll
        for (int mi = 0; mi < 2; mi++) {
            int ar = mb + mi * 16 + g;
            split_tf32(sA[ar * LDSS + k0],           ah[mi][0], al[mi][0]);
            split_tf32(sA[(ar + 8) * LDSS + k0],     ah[mi][1], al[mi][1]);
            split_tf32(sA[ar * LDSS + k0 + 4],       ah[mi][2], al[mi][2]);
            split_tf32(sA[(ar + 8) * LDSS + k0 + 4], ah[mi][3], al[mi][3]);
        }
        #pragma unroll
        for (int ni = 0; ni < 4; ni++) {
            int bn = nb + ni * 8 + g;
            split_tf32(sB[bn * LDSS + k0],     bh[ni][0], bl[ni][0]);
            split_tf32(sB[bn * LDSS + k0 + 4], bh[ni][1], bl[ni][1]);
        }
        #pragma unroll
        for (int mi = 0; mi < 2; mi++)
            #pragma unroll
            for (int ni = 0; ni < 4; ni++) {
                mma8(acc[mi][ni], al[mi], bh[ni]);
                mma8(acc[mi][ni], ah[mi], bl[ni]);
                mma8(acc[mi][ni], ah[mi], bh[ni]);
            }
    }
}

// ---------------- parallel GEMMs: modes 0/1 (pre f/b), 2 (novelty) ---------
// 512 threads, block tile 128x128, 16 warps (4m x 4n), 3-stage pipeline.
__global__ void __launch_bounds__(512) k_mma_gemm(
    const float* __restrict__ A,
    const float* __restrict__ W,
    const float* __restrict__ bias,
    int K, int mode)
{
    extern __shared__ __align__(16) float sm[];
    if (mode == 2) { A = &g_sents[0]; W = &g_WnovT[0]; }
    float*   sA[3]; float*   sB[3];
    unsigned uA[3]; unsigned uB[3];
    #pragma unroll
    for (int s = 0; s < 3; s++) {
        sA[s] = sm + s * (TILEA_F + TILEB_F);
        sB[s] = sA[s] + TILEA_F;
        uA[s] = smem_u32(sA[s]);
        uB[s] = smem_u32(sB[s]);
    }
    int tid = threadIdx.x, lane = tid & 31, wid = tid >> 5;
    int mb = (wid >> 2) * 32, nb = (wid & 3) * 32;
    int n0 = blockIdx.x * 128, m0 = blockIdx.y * 128;
    const float* Ab = A + (size_t)m0 * K;
    const float* Wb = W + (size_t)n0 * K;

    float acc[2][4][4];
    #pragma unroll
    for (int i = 0; i < 2; i++)
        #pragma unroll
        for (int j = 0; j < 4; j++)
            #pragma unroll
            for (int q = 0; q < 4; q++) acc[i][j][q] = 0.f;

    int NC = K >> 5;
    ld128_t512(Ab,      K, uA[0], tid); ld128_t512(Wb,      K, uB[0], tid); cp_commit();
    ld128_t512(Ab + 32, K, uA[1], tid); ld128_t512(Wb + 32, K, uB[1], tid); cp_commit();

    for (int i = 0; i < NC; i++) {
        if (i == NC - 1) cp_wait0(); else cp_wait1();
        __syncthreads();
        if (i + 2 < NC) {
            int s = (i + 2) % 3;
            size_t o = (size_t)(i + 2) * 32;
            ld128_t512(Ab + o, K, uA[s], tid);
            ld128_t512(Wb + o, K, uB[s], tid);
            cp_commit();
        }
        int p = i % 3;
        compute_warp32(sA[p], sB[p], mb, nb, lane, acc);
    }

    int g = lane >> 2, tig = lane & 3;
    #pragma unroll
    for (int mi = 0; mi < 2; mi++) {
        #pragma unroll
        for (int ni = 0; ni < 4; ni++) {
            int n = n0 + nb + ni * 8 + tig * 2;
            float2 bs = make_float2(0.f, 0.f);
            if (bias) bs = *(const float2*)(bias + n);
            #pragma unroll
            for (int hf = 0; hf < 2; hf++) {
                int m = m0 + mb + mi * 16 + g + hf * 8;
                float2 v = make_float2(acc[mi][ni][hf * 2 + 0] + bs.x,
                                       acc[mi][ni][hf * 2 + 1] + bs.y);
                if (mode < 2) {
                    int t = m >> 6, b = m & 63;
                    *(float2*)&g_pre[mode][(((size_t)b * TT + t) * GG) + n] = v;
                } else {
                    *(float2*)&g_hW[(size_t)m * H2 + n] = v;
                }
            }
        }
    }
}

// ---------------- recurrence step: M64 x N128, fused LSTM activation -------
// grid (512/32=16 j-tiles, 256/64=4 t-tiles, 2 dirs) = 128 blocks, 256 thr.
// N=128 covers 4 gates x 32 j.
#define GBSR 132
__global__ void __launch_bounds__(256) k_mma_rec(
    const float* __restrict__ w_hh_f,
    const float* __restrict__ w_hh_b,
    int pp, int b_f, int b_b)
{
    extern __shared__ __align__(16) float sm[];
    int dir = blockIdx.z;
    const float* A = &g_h[pp][dir][0];
    const float* W = dir ? w_hh_b : w_hh_f;
    int b = dir ? b_b : b_f;
    int j0 = blockIdx.x * 32;
    int m0 = blockIdx.y * 64;

    float*   sA[3]; float*   sB[3];
    unsigned uA[3]; unsigned uB[3];
    #pragma unroll
    for (int s = 0; s < 3; s++) {
        sA[s] = sm + s * (TILE64_F + TILEB_F);
        sB[s] = sA[s] + TILE64_F;
        uA[s] = smem_u32(sA[s]);
        uB[s] = smem_u32(sB[s]);
    }
    int tid = threadIdx.x, lane = tid & 31, wid = tid >> 5;
    int mb = (wid >> 2) * 32, nb = (wid & 3) * 32;

    float acc[2][4][4];
    #pragma unroll
    for (int i = 0; i < 2; i++)
        #pragma unroll
        for (int j = 0; j < 4; j++)
            #pragma unroll
            for (int q = 0; q < 4; q++) acc[i][j][q] = 0.f;

    const int NC = HH >> 5;   // 16
    const float* Ab = A + (size_t)m0 * HH;
    ld64_t256(Ab,      HH, uA[0], tid); ld128gate_t256(W, j0, 0,  uB[0], tid); cp_commit();
    ld64_t256(Ab + 32, HH, uA[1], tid); ld128gate_t256(W, j0, 32, uB[1], tid); cp_commit();

    for (int i = 0; i < NC; i++) {
        if (i == NC - 1) cp_wait0(); else cp_wait1();
        __syncthreads();
        if (i + 2 < NC) {
            int s = (i + 2) % 3;
            int ko = (i + 2) * 32;
            ld64_t256(Ab + ko, HH, uA[s], tid);
            ld128gate_t256(W, j0, ko, uB[s], tid);
            cp_commit();
        }
        int p = i % 3;
        compute_warp32(sA[p], sB[p], mb, nb, lane, acc);
    }
    __syncthreads();   // all reads of smem tiles done before reuse as gate buffer

    // stash gate pre-acts: gb[t_local][n_local], n_local = gate*32 + jj
    float* gb = sm;    // 64*132*4 = 33792 <= SMEM_R
    int g = lane >> 2, tig = lane & 3;
    #pragma unroll
    for (int mi = 0; mi < 2; mi++) {
        #pragma unroll
        for (int ni = 0; ni < 4; ni++) {
            int col = nb + ni * 8 + tig * 2;
            #pragma unroll
            for (int hf = 0; hf < 2; hf++) {
                int row = mb + mi * 16 + g + hf * 8;
                gb[row * GBSR + col]     = acc[mi][ni][hf * 2 + 0];
                gb[row * GBSR + col + 1] = acc[mi][ni][hf * 2 + 1];
            }
        }
    }
    __syncthreads();

    // fused LSTM cell update: 64 t x 32 j items, 8 per thread
    #pragma unroll
    for (int it = 0; it < 8; it++) {
        int id = tid + it * 256;
        int tl = id >> 5, jj = id & 31;
        int tg = m0 + tl;
        int jg = j0 + jj;
        size_t preb = ((size_t)b * TT + tg) * GG;
        float vi = gb[tl * GBSR +  0 + jj] + g_pre[dir][preb +    0 + jg];
        float vf = gb[tl * GBSR + 32 + jj] + g_pre[dir][preb +  512 + jg];
        float vg = gb[tl * GBSR + 64 + jj] + g_pre[dir][preb + 1024 + jg];
        float vo = gb[tl * GBSR + 96 + jj] + g_pre[dir][preb + 1536 + jg];
        float c  = g_c[dir][tg * HH + jg];
        float si = 1.f / (1.f + expf(-vi));
        float sf = 1.f / (1.f + expf(-vf));
        float so = 1.f / (1.f + expf(-vo));
        float cn = sf * c + si * tanhf(vg);
        float h  = so * tanhf(cn);
        g_c[dir][tg * HH + jg] = cn;
        g_h[pp ^ 1][dir][tg * HH + jg] = h;
        g_sents[(((size_t)tg * BB + b) * H2) + dir * HH + jg] = h;
    }
}

// ---------------- transpose W_nov (K-major B for the nn GEMM) ---------------
__global__ void k_transpose(const float* __restrict__ W) {
    __shared__ float ts[32][33];
    int bx = blockIdx.x * 32, by = blockIdx.y * 32;
    int tx = threadIdx.x, ty = threadIdx.y;   // 32 x 8
    #pragma unroll
    for (int q = 0; q < 4; q++)
        ts[ty + 8*q][tx] = W[(size_t)(by + ty + 8*q) * H2 + bx + tx];
    __syncthreads();
    #pragma unroll
    for (int q = 0; q < 4; q++)
        g_WnovT[(size_t)(bx + ty + 8*q) * H2 + by + tx] = ts[tx][ty + 8*q];
}

// ---------------- init -----------------------------------------------------
__global__ void k_zero() {
    int i = blockIdx.x * blockDim.x + threadIdx.x;
    if (i < 2*TT*HH) {
        (&g_h[0][0][0])[i] = 0.f;
        (&g_c[0][0])[i]    = 0.f;
    }
}

// ---------------- doc pipeline ----------------------------------------------
__global__ void k_docmean() {
    int idx = blockIdx.x * blockDim.x + threadIdx.x;
    int b = idx >> 10, h = idx & 1023;
    float s = 0.f;
    for (int t = 0; t < TT; t++) s += g_sents[(((size_t)t*BB + b)*H2) + h];
    g_docmean[b*H2 + h] = s * (1.f/TT);
}

__global__ void k_doc(const float* __restrict__ W_fdoc, const float* __restrict__ b_fdoc) {
    int w = blockIdx.x*8 + (threadIdx.x >> 5);
    int lane = threadIdx.x & 31;
    int b = w >> 10, n = w & 1023;
    const float* wr = &W_fdoc[(size_t)n*H2];
    const float* dm = &g_docmean[b*H2];
    float s = 0.f;
    for (int k = lane; k < H2; k += 32) s += wr[k]*dm[k];
    #pragma unroll
    for (int o = 16; o > 0; o >>= 1) s += __shfl_down_sync(0xffffffffu, s, o);
    if (lane == 0) g_doc[b*H2 + n] = tanhf(s + b_fdoc[n]);
}

__global__ void k_u(const float* __restrict__ W_sal, const float* __restrict__ w_content) {
    int w = blockIdx.x*8 + (threadIdx.x >> 5);
    int lane = threadIdx.x & 31;
    int b = w >> 10, h = w & 1023;
    const float* wr = &W_sal[(size_t)h*H2];
    const float* dc = &g_doc[b*H2];
    float s = 0.f;
    for (int k = lane; k < H2; k += 32) s += wr[k]*dc[k];
    #pragma unroll
    for (int o = 16; o > 0; o >>= 1) s += __shfl_down_sync(0xffffffffu, s, o);
    if (lane == 0) g_u[b*H2 + h] = s + w_content[h];
}

__global__ void k_absp(const float* __restrict__ pos_emb, const float* __restrict__ w_abs) {
    int t = threadIdx.x;
    float s = 0.f;
    for (int p = 0; p < 100; p++) s += pos_emb[t*100 + p]*w_abs[p];
    g_absp[t] = s;
}

__global__ void k_s0(const float* __restrict__ bias) {
    int w = blockIdx.x*8 + (threadIdx.x >> 5);
    int lane = threadIdx.x & 31;
    int b = w >> 8, t = w & 255;
    const float* sp = &g_sents[((size_t)t*BB + b)*H2];
    const float* up = &g_u[b*H2];
    float s = 0.f;
    for (int k = lane; k < H2; k += 32) s += sp[k]*up[k];
    #pragma unroll
    for (int o = 16; o > 0; o >>= 1) s += __shfl_down_sync(0xffffffffu, s, o);
    if (lane == 0) g_s0[b*TT + t] = s + g_absp[t] + bias[0];
}

// ---------------- final sequential scan (independent per b) -----------------
__global__ void k_scan(float* __restrict__ out) {
    __shared__ float summ[H2];
    __shared__ float red[8];
    __shared__ float probsh;
    int b = blockIdx.x;
    int tid = threadIdx.x;
    int lane = tid & 31, wrp = tid >> 5;
    #pragma unroll
    for (int q = 0; q < 4; q++) summ[tid + q*256] = 0.f;
    __syncthreads();
    for (int t = 0; t < TT; t++) {
        const float* hw = &g_hW[((size_t)t*BB + b)*H2];
        float part = 0.f;
        #pragma unroll
        for (int q = 0; q < 4; q++) {
            int k = tid + q*256;
            part += hw[k]*tanhf(summ[k]);
        }
        #pragma unroll
        for (int o = 16; o > 0; o >>= 1) part += __shfl_down_sync(0xffffffffu, part, o);
        if (lane == 0) red[wrp] = part;
        __syncthreads();
        if (tid == 0) {
            float nov = 0.f;
            #pragma unroll
            for (int r = 0; r < 8; r++) nov += red[r];
            float prob = 1.f/(1.f+expf(-(g_s0[b*TT + t] - nov)));
            out[b*TT + t] = prob;
            probsh = prob;
        }
        __syncthreads();
        float p = probsh;
        const float* sp = &g_sents[((size_t)t*BB + b)*H2];
        #pragma unroll
        for (int q = 0; q < 4; q++) {
            int k = tid + q*256;
            summ[k] += p * sp[k];
        }
        __syncthreads();
    }
}

// ---------------- launcher ---------------------------------------------------
extern "C" void kernel_launch(void* const* d_in, const int* in_sizes, int n_in,
                              void* d_out, int out_size) {
    const float* emb      = (const float*)d_in[0];
    const float* w_ih_f   = (const float*)d_in[2];
    const float* w_hh_f   = (const float*)d_in[3];
    const float* b_f      = (const float*)d_in[4];
    const float* w_ih_b   = (const float*)d_in[5];
    const float* w_hh_b   = (const float*)d_in[6];
    const float* b_b      = (const float*)d_in[7];
    const float* W_fdoc   = (const float*)d_in[8];
    const float* b_fdoc   = (const float*)d_in[9];
    const float* pos_emb  = (const float*)d_in[10];
    const float* w_content= (const float*)d_in[11];
    const float* W_sal    = (const float*)d_in[12];
    const float* W_nov    = (const float*)d_in[13];
    const float* w_abs    = (const float*)d_in[14];
    const float* bias     = (const float*)d_in[15];
    float* out = (float*)d_out;

    cudaFuncSetAttribute(k_mma_gemm, cudaFuncAttributeMaxDynamicSharedMemorySize, SMEM_G);
    cudaFuncSetAttribute(k_mma_rec,  cudaFuncAttributeMaxDynamicSharedMemorySize, SMEM_R);

    k_zero<<<1024, 256>>>();
    k_transpose<<<dim3(32, 32), dim3(32, 8)>>>(W_nov);

    // input projections (3xTF32 MMA, bias fused, permuted store)
    dim3 gpre(GG/128, TB/128);             // 16 x 128
    k_mma_gemm<<<gpre, 512, SMEM_G>>>(emb, w_ih_f, b_f, EE, 0);
    k_mma_gemm<<<gpre, 512, SMEM_G>>>(emb, w_ih_b, b_b, EE, 1);

    // recurrence: 64 steps, 128 blocks each, fused LSTM activation
    for (int s = 0; s < BB; s++) {
        dim3 grec(HH/32, TT/64, 2);        // 16 x 4 x 2
        k_mma_rec<<<grec, 256, SMEM_R>>>(w_hh_f, w_hh_b, s & 1, s, 63 - s);
    }

    k_docmean<<<256, 256>>>();
    k_doc<<<8192, 256>>>(W_fdoc, b_fdoc);
    k_u<<<8192, 256>>>(W_sal, w_content);
    k_absp<<<1, 256>>>(pos_emb, w_abs);
    k_s0<<<2048, 256>>>(bias);

    // novelty GEMM (A = g_sents, W = g_WnovT resolved in-kernel)
    dim3 gnn(H2/128, TB/128);              // 8 x 128
    k_mma_gemm<<<gnn, 512, SMEM_G>>>(nullptr, nullptr, nullptr, H2, 2);

    k_scan<<<BB, 256>>>(out);
}

// round 8
// speedup vs baseline: 1.1354x; 1.1354x over previous
#include <cuda_runtime.h>
#include <math.h>

// Problem dims
#define TT 256
#define BB 64
#define EE 768
#define HH 512
#define H2 1024
#define GG 2048            // 4*H
#define TB (TT*BB)         // 16384

// ---------------- scratch (device globals; no allocation allowed) ----------
__device__ float g_pre[2][(size_t)BB*TT*GG];   // [dir][b][t][g]  (bias included)
__device__ float g_h[2][2][TT*HH];             // [pingpong][dir][t*H+j]
__device__ float g_c[2][TT*HH];                // [dir][t*H+j]
__device__ float g_sents[(size_t)TB*H2];       // [t][b][h2]
__device__ float g_hW[(size_t)TB*H2];          // [t][b][k]
__device__ float g_WnovT[(size_t)H2*H2];       // W_nov transposed (K-major)
__device__ float g_docmean[BB*H2];
__device__ float g_doc[BB*H2];
__device__ float g_u[BB*H2];
__device__ float g_absp[TT];
__device__ float g_s0[BB*TT];

// =========================================================================
// mma.sync 3xTF32 GEMM machinery (in-loop split; round-5 proven config)
// Block tile 128x128, K-chunk 32, 256 threads = 8 warps (2M x 4N),
// warp tile 64x32, cp.async double buffer. launch_bounds(256,2) for 2 CTA/SM.
// =========================================================================
#define LDSS 36                         // smem row stride (floats)
#define TILE_F (128*LDSS)
#define SMEM_BYTES (4*TILE_F*4)         // A0,A1,B0,B1 = 73728 B

// rec kernel: 64-row tiles
#define TILE64_F (64*LDSS)
#define SMEM_REC (4*TILE64_F*4)         // 36864 B

__device__ __forceinline__ unsigned smem_u32(const void* p) {
    unsigned a;
    asm("{ .reg .u64 t; cvta.to.shared.u64 t, %1; cvt.u32.u64 %0, t; }"
        : "=r"(a) : "l"(p));
    return a;
}
__device__ __forceinline__ void cp16(unsigned s, const float* g) {
    asm volatile("cp.async.cg.shared.global [%0], [%1], 16;"
                 :: "r"(s), "l"(__cvta_generic_to_global((void*)g)));
}
__device__ __forceinline__ void cp_commit() {
    asm volatile("cp.async.commit_group;" ::: "memory");
}
__device__ __forceinline__ void cp_wait1() {
    asm volatile("cp.async.wait_group 1;" ::: "memory");
}
__device__ __forceinline__ void cp_wait0() {
    asm volatile("cp.async.wait_group 0;" ::: "memory");
}
__device__ __forceinline__ void mma8(float c[4], const unsigned a[4], const unsigned b[2]) {
    asm volatile(
        "mma.sync.aligned.m16n8k8.row.col.f32.tf32.tf32.f32 "
        "{%0,%1,%2,%3}, {%4,%5,%6,%7}, {%8,%9}, {%0,%1,%2,%3};\n"
        : "+f"(c[0]), "+f"(c[1]), "+f"(c[2]), "+f"(c[3])
        : "r"(a[0]), "r"(a[1]), "r"(a[2]), "r"(a[3]), "r"(b[0]), "r"(b[1]));
}
__device__ __forceinline__ unsigned cvt_tf32(float f) {
    unsigned u;
    asm("cvt.rna.tf32.f32 %0, %1;" : "=r"(u) : "f"(f));
    return u;
}
__device__ __forceinline__ void split_tf32(float f, unsigned& hi, unsigned& lo) {
    hi = cvt_tf32(f);
    lo = cvt_tf32(f - __uint_as_float(hi));
}

// load a 128-row x 32-float K-chunk into smem tile (256 threads)
__device__ __forceinline__ void load_chunk(const float* __restrict__ gsrc, int ldg,
                                           unsigned sbase, int tid) {
    int r0 = tid >> 3;
    int c  = (tid & 7) * 4;
    const float* gp = gsrc + (size_t)r0 * ldg + c;
    unsigned sp = sbase + (unsigned)((r0 * LDSS + c) * 4);
    #pragma unroll
    for (int q = 0; q < 4; q++) {
        cp16(sp, gp);
        gp += (size_t)32 * ldg;
        sp += 32 * LDSS * 4;
    }
}
// 64-row x 32-float chunk loaders (128 threads)
__device__ __forceinline__ void load_chunk64(const float* __restrict__ gsrc, int ldg,
                                             unsigned sbase, int tid) {
    #pragma unroll
    for (int q = 0; q < 4; q++) {
        int idx = q * 128 + tid;
        int row = idx >> 3;
        int c   = (idx & 7) * 4;
        cp16(sbase + (unsigned)((row * LDSS + c) * 4),
             gsrc + (size_t)row * ldg + c);
    }
}
// gate-grouped B rows: logical row r -> W row (r>>4)*512 + j0 + (r&15)
__device__ __forceinline__ void load_chunk64_gate(const float* __restrict__ W, int j0,
                                                  int koff, unsigned sbase, int tid) {
    #pragma unroll
    for (int q = 0; q < 4; q++) {
        int idx = q * 128 + tid;
        int row = idx >> 3;
        int c   = (idx & 7) * 4;
        int grow = (row >> 4) * 512 + j0 + (row & 15);
        cp16(sbase + (unsigned)((row * LDSS + c) * 4),
             W + (size_t)grow * HH + koff + c);
    }
}

// 256-thread compute: warp tile 64x32 (wm 0..1, wn 0..3)
__device__ __forceinline__ void compute_chunk(const float* sA, const float* sB,
                                              int wm, int wn, int lane,
                                              float acc[4][4][4]) {
    int g = lane >> 2, tig = lane & 3;
    #pragma unroll
    for (int kk = 0; kk < 4; kk++) {
        int k0 = kk * 8 + tig;
        unsigned ah[4][4], al[4][4], bh[4][2], bl[4][2];
        #pragma unroll
        for (int mi = 0; mi < 4; mi++) {
            int ar = wm * 64 + mi * 16 + g;
            split_tf32(sA[ar * LDSS + k0],           ah[mi][0], al[mi][0]);
            split_tf32(sA[(ar + 8) * LDSS + k0],     ah[mi][1], al[mi][1]);
            split_tf32(sA[ar * LDSS + k0 + 4],       ah[mi][2], al[mi][2]);
            split_tf32(sA[(ar + 8) * LDSS + k0 + 4], ah[mi][3], al[mi][3]);
        }
        #pragma unroll
        for (int ni = 0; ni < 4; ni++) {
            int bn = wn * 32 + ni * 8 + g;
            split_tf32(sB[bn * LDSS + k0],     bh[ni][0], bl[ni][0]);
            split_tf32(sB[bn * LDSS + k0 + 4], bh[ni][1], bl[ni][1]);
        }
        #pragma unroll
        for (int mi = 0; mi < 4; mi++)
            #pragma unroll
            for (int ni = 0; ni < 4; ni++) {
                mma8(acc[mi][ni], al[mi], bh[ni]);
                mma8(acc[mi][ni], ah[mi], bl[ni]);
                mma8(acc[mi][ni], ah[mi], bh[ni]);
            }
    }
}

// 128-thread compute: warp tile 32x32 (wm 0..1, wn 0..1)
__device__ __forceinline__ void compute_chunk64(const float* sA, const float* sB,
                                                int wm, int wn, int lane,
                                                float acc[2][4][4]) {
    int g = lane >> 2, tig = lane & 3;
    #pragma unroll
    for (int kk = 0; kk < 4; kk++) {
        int k0 = kk * 8 + tig;
        unsigned ah[2][4], al[2][4], bh[4][2], bl[4][2];
        #pragma unroll
        for (int mi = 0; mi < 2; mi++) {
            int ar = wm * 32 + mi * 16 + g;
            split_tf32(sA[ar * LDSS + k0],           ah[mi][0], al[mi][0]);
            split_tf32(sA[(ar + 8) * LDSS + k0],     ah[mi][1], al[mi][1]);
            split_tf32(sA[ar * LDSS + k0 + 4],       ah[mi][2], al[mi][2]);
            split_tf32(sA[(ar + 8) * LDSS + k0 + 4], ah[mi][3], al[mi][3]);
        }
        #pragma unroll
        for (int ni = 0; ni < 4; ni++) {
            int bn = wn * 32 + ni * 8 + g;
            split_tf32(sB[bn * LDSS + k0],     bh[ni][0], bl[ni][0]);
            split_tf32(sB[bn * LDSS + k0 + 4], bh[ni][1], bl[ni][1]);
        }
        #pragma unroll
        for (int mi = 0; mi < 2; mi++)
            #pragma unroll
            for (int ni = 0; ni < 4; ni++) {
                mma8(acc[mi][ni], al[mi], bh[ni]);
                mma8(acc[mi][ni], ah[mi], bl[ni]);
                mma8(acc[mi][ni], ah[mi], bh[ni]);
            }
    }
}

// ---------------- parallel GEMMs ---------------------------------------------
// mode 0: fused input projections, grid.z = dir (W/bias/output per dir)
// mode 2: novelty GEMM (A = g_sents, W = g_WnovT), grid.z = 1
__global__ void __launch_bounds__(256, 2) k_mma_gemm(
    const float* __restrict__ A,
    const float* __restrict__ W0,
    const float* __restrict__ W1,
    const float* __restrict__ bias0,
    const float* __restrict__ bias1,
    int K, int mode)
{
    extern __shared__ __align__(16) float sm[];
    int dir = blockIdx.z;
    const float* W;
    const float* bias;
    if (mode == 2) { A = &g_sents[0]; W = &g_WnovT[0]; bias = nullptr; }
    else           { W = dir ? W1 : W0; bias = dir ? bias1 : bias0; }

    float* sA[2] = { sm, sm + TILE_F };
    float* sB[2] = { sm + 2 * TILE_F, sm + 3 * TILE_F };
    unsigned sAu[2] = { smem_u32(sA[0]), smem_u32(sA[1]) };
    unsigned sBu[2] = { smem_u32(sB[0]), smem_u32(sB[1]) };
    int tid = threadIdx.x, lane = tid & 31, wid = tid >> 5;
    int wm = wid >> 2, wn = wid & 3;
    int n0 = blockIdx.x * 128, m0 = blockIdx.y * 128;
    const float* Ab = A + (size_t)m0 * K;
    const float* Wb = W + (size_t)n0 * K;

    float acc[4][4][4];
    #pragma unroll
    for (int i = 0; i < 4; i++)
        #pragma unroll
        for (int j = 0; j < 4; j++)
            #pragma unroll
            for (int q = 0; q < 4; q++) acc[i][j][q] = 0.f;

    int NC = K >> 5;
    load_chunk(Ab, K, sAu[0], tid); load_chunk(Wb, K, sBu[0], tid); cp_commit();
    load_chunk(Ab + 32, K, sAu[1], tid); load_chunk(Wb + 32, K, sBu[1], tid); cp_commit();

    for (int i = 0; i < NC; i++) {
        if (i + 1 < NC) cp_wait1(); else cp_wait0();
        __syncthreads();
        int p = i & 1;
        compute_chunk(sA[p], sB[p], wm, wn, lane, acc);
        __syncthreads();
        if (i + 2 < NC) {
            load_chunk(Ab + (size_t)(i + 2) * 32, K, sAu[p], tid);
            load_chunk(Wb + (size_t)(i + 2) * 32, K, sBu[p], tid);
            cp_commit();
        }
    }

    int g = lane >> 2, tig = lane & 3;
    #pragma unroll
    for (int mi = 0; mi < 4; mi++) {
        #pragma unroll
        for (int ni = 0; ni < 4; ni++) {
            int n = n0 + wn * 32 + ni * 8 + tig * 2;
            float2 bs = make_float2(0.f, 0.f);
            if (bias) bs = *(const float2*)(bias + n);
            #pragma unroll
            for (int hf = 0; hf < 2; hf++) {
                int m = m0 + wm * 64 + mi * 16 + g + hf * 8;
                float2 v = make_float2(acc[mi][ni][hf * 2 + 0] + bs.x,
                                       acc[mi][ni][hf * 2 + 1] + bs.y);
                if (mode < 2) {
                    int t = m >> 6, b = m & 63;
                    *(float2*)&g_pre[dir][(((size_t)b * TT + t) * GG) + n] = v;
                } else {
                    *(float2*)&g_hW[(size_t)m * H2 + n] = v;
                }
            }
        }
    }
}

// ---------------- recurrence step: 64x64 tiles (round-5 proven) ------------
#define GBS64 68
__global__ void __launch_bounds__(128) k_mma_rec(
    const float* __restrict__ w_hh_f,
    const float* __restrict__ w_hh_b,
    int pp, int b_f, int b_b)
{
    extern __shared__ __align__(16) float sm[];
    int dir = blockIdx.z;
    const float* A = &g_h[pp][dir][0];
    const float* W = dir ? w_hh_b : w_hh_f;
    int b = dir ? b_b : b_f;
    int j0 = blockIdx.x * 16;
    int m0 = blockIdx.y * 64;

    float* sA[2] = { sm, sm + TILE64_F };
    float* sB[2] = { sm + 2 * TILE64_F, sm + 3 * TILE64_F };
    unsigned sAu[2] = { smem_u32(sA[0]), smem_u32(sA[1]) };
    unsigned sBu[2] = { smem_u32(sB[0]), smem_u32(sB[1]) };
    int tid = threadIdx.x, lane = tid & 31, wid = tid >> 5;
    int wm = wid >> 1, wn = wid & 1;

    float acc[2][4][4];
    #pragma unroll
    for (int i = 0; i < 2; i++)
        #pragma unroll
        for (int j = 0; j < 4; j++)
            #pragma unroll
            for (int q = 0; q < 4; q++) acc[i][j][q] = 0.f;

    const int NC = HH >> 5;   // 16
    const float* Ab = A + (size_t)m0 * HH;
    load_chunk64(Ab, HH, sAu[0], tid); load_chunk64_gate(W, j0, 0, sBu[0], tid); cp_commit();
    load_chunk64(Ab + 32, HH, sAu[1], tid); load_chunk64_gate(W, j0, 32, sBu[1], tid); cp_commit();

    for (int i = 0; i < NC; i++) {
        if (i + 1 < NC) cp_wait1(); else cp_wait0();
        __syncthreads();
        int p = i & 1;
        compute_chunk64(sA[p], sB[p], wm, wn, lane, acc);
        __syncthreads();
        if (i + 2 < NC) {
            int ko = (i + 2) * 32;
            load_chunk64(Ab + ko, HH, sAu[p], tid);
            load_chunk64_gate(W, j0, ko, sBu[p], tid);
            cp_commit();
        }
    }

    // stash gate pre-acts: gb[t_local][n_local], n_local = gate*16 + jj
    float* gb = sm;   // 64*68*4 = 17408 <= SMEM_REC
    int g = lane >> 2, tig = lane & 3;
    #pragma unroll
    for (int mi = 0; mi < 2; mi++) {
        #pragma unroll
        for (int ni = 0; ni < 4; ni++) {
            int col = wn * 32 + ni * 8 + tig * 2;
            #pragma unroll
            for (int hf = 0; hf < 2; hf++) {
                int row = wm * 32 + mi * 16 + g + hf * 8;
                gb[row * GBS64 + col]     = acc[mi][ni][hf * 2 + 0];
                gb[row * GBS64 + col + 1] = acc[mi][ni][hf * 2 + 1];
            }
        }
    }
    __syncthreads();

    // fused LSTM cell update: 64 t x 16 j items, 8 per thread
    #pragma unroll
    for (int it = 0; it < 8; it++) {
        int id = tid + it * 128;
        int tl = id >> 4, jj = id & 15;
        int tg = m0 + tl;
        int jg = j0 + jj;
        size_t preb = ((size_t)b * TT + tg) * GG;
        float vi = gb[tl * GBS64 +  0 + jj] + g_pre[dir][preb +    0 + jg];
        float vf = gb[tl * GBS64 + 16 + jj] + g_pre[dir][preb +  512 + jg];
        float vg = gb[tl * GBS64 + 32 + jj] + g_pre[dir][preb + 1024 + jg];
        float vo = gb[tl * GBS64 + 48 + jj] + g_pre[dir][preb + 1536 + jg];
        float c  = g_c[dir][tg * HH + jg];
        float si = 1.f / (1.f + expf(-vi));
        float sf = 1.f / (1.f + expf(-vf));
        float so = 1.f / (1.f + expf(-vo));
        float cn = sf * c + si * tanhf(vg);
        float h  = so * tanhf(cn);
        g_c[dir][tg * HH + jg] = cn;
        g_h[pp ^ 1][dir][tg * HH + jg] = h;
        g_sents[(((size_t)tg * BB + b) * H2) + dir * HH + jg] = h;
    }
}

// ---------------- transpose W_nov (K-major B for the nn GEMM) ---------------
__global__ void k_transpose(const float* __restrict__ W) {
    __shared__ float ts[32][33];
    int bx = blockIdx.x * 32, by = blockIdx.y * 32;
    int tx = threadIdx.x, ty = threadIdx.y;   // 32 x 8
    #pragma unroll
    for (int q = 0; q < 4; q++)
        ts[ty + 8*q][tx] = W[(size_t)(by + ty + 8*q) * H2 + bx + tx];
    __syncthreads();
    #pragma unroll
    for (int q = 0; q < 4; q++)
        g_WnovT[(size_t)(bx + ty + 8*q) * H2 + by + tx] = ts[tx][ty + 8*q];
}

// ---------------- init -----------------------------------------------------
__global__ void k_zero() {
    int i = blockIdx.x * blockDim.x + threadIdx.x;
    if (i < 2*TT*HH) {
        (&g_h[0][0][0])[i] = 0.f;
        (&g_c[0][0])[i]    = 0.f;
    }
}

// ---------------- doc pipeline ----------------------------------------------
__global__ void k_docmean() {
    int idx = blockIdx.x * blockDim.x + threadIdx.x;
    int b = idx >> 10, h = idx & 1023;
    float s = 0.f;
    for (int t = 0; t < TT; t++) s += g_sents[(((size_t)t*BB + b)*H2) + h];
    g_docmean[b*H2 + h] = s * (1.f/TT);
}

__global__ void k_doc(const float* __restrict__ W_fdoc, const float* __restrict__ b_fdoc) {
    int w = blockIdx.x*8 + (threadIdx.x >> 5);
    int lane = threadIdx.x & 31;
    int b = w >> 10, n = w & 1023;
    const float* wr = &W_fdoc[(size_t)n*H2];
    const float* dm = &g_docmean[b*H2];
    float s = 0.f;
    for (int k = lane; k < H2; k += 32) s += wr[k]*dm[k];
    #pragma unroll
    for (int o = 16; o > 0; o >>= 1) s += __shfl_down_sync(0xffffffffu, s, o);
    if (lane == 0) g_doc[b*H2 + n] = tanhf(s + b_fdoc[n]);
}

__global__ void k_u(const float* __restrict__ W_sal, const float* __restrict__ w_content) {
    int w = blockIdx.x*8 + (threadIdx.x >> 5);
    int lane = threadIdx.x & 31;
    int b = w >> 10, h = w & 1023;
    const float* wr = &W_sal[(size_t)h*H2];
    const float* dc = &g_doc[b*H2];
    float s = 0.f;
    for (int k = lane; k < H2; k += 32) s += wr[k]*dc[k];
    #pragma unroll
    for (int o = 16; o > 0; o >>= 1) s += __shfl_down_sync(0xffffffffu, s, o);
    if (lane == 0) g_u[b*H2 + h] = s + w_content[h];
}

__global__ void k_absp(const float* __restrict__ pos_emb, const float* __restrict__ w_abs) {
    int t = threadIdx.x;
    float s = 0.f;
    for (int p = 0; p < 100; p++) s += pos_emb[t*100 + p]*w_abs[p];
    g_absp[t] = s;
}

__global__ void k_s0(const float* __restrict__ bias) {
    int w = blockIdx.x*8 + (threadIdx.x >> 5);
    int lane = threadIdx.x & 31;
    int b = w >> 8, t = w & 255;
    const float* sp = &g_sents[((size_t)t*BB + b)*H2];
    const float* up = &g_u[b*H2];
    float s = 0.f;
    for (int k = lane; k < H2; k += 32) s += sp[k]*up[k];
    #pragma unroll
    for (int o = 16; o > 0; o >>= 1) s += __shfl_down_sync(0xffffffffu, s, o);
    if (lane == 0) g_s0[b*TT + t] = s + g_absp[t] + bias[0];
}

// ---------------- final sequential scan (independent per b) -----------------
__global__ void k_scan(float* __restrict__ out) {
    __shared__ float summ[H2];
    __shared__ float red[8];
    __shared__ float probsh;
    int b = blockIdx.x;
    int tid = threadIdx.x;
    int lane = tid & 31, wrp = tid >> 5;
    #pragma unroll
    for (int q = 0; q < 4; q++) summ[tid + q*256] = 0.f;
    __syncthreads();
    for (int t = 0; t < TT; t++) {
        const float* hw = &g_hW[((size_t)t*BB + b)*H2];
        float part = 0.f;
        #pragma unroll
        for (int q = 0; q < 4; q++) {
            int k = tid + q*256;
            part += hw[k]*tanhf(summ[k]);
        }
        #pragma unroll
        for (int o = 16; o > 0; o >>= 1) part += __shfl_down_sync(0xffffffffu, part, o);
        if (lane == 0) red[wrp] = part;
        __syncthreads();
        if (tid == 0) {
            float nov = 0.f;
            #pragma unroll
            for (int r = 0; r < 8; r++) nov += red[r];
            float prob = 1.f/(1.f+expf(-(g_s0[b*TT + t] - nov)));
            out[b*TT + t] = prob;
            probsh = prob;
        }
        __syncthreads();
        float p = probsh;
        const float* sp = &g_sents[((size_t)t*BB + b)*H2];
        #pragma unroll
        for (int q = 0; q < 4; q++) {
            int k = tid + q*256;
            summ[k] += p * sp[k];
        }
        __syncthreads();
    }
}

// ---------------- launcher ---------------------------------------------------
extern "C" void kernel_launch(void* const* d_in, const int* in_sizes, int n_in,
                              void* d_out, int out_size) {
    const float* emb      = (const float*)d_in[0];
    const float* w_ih_f   = (const float*)d_in[2];
    const float* w_hh_f   = (const float*)d_in[3];
    const float* b_f      = (const float*)d_in[4];
    const float* w_ih_b   = (const float*)d_in[5];
    const float* w_hh_b   = (const float*)d_in[6];
    const float* b_b      = (const float*)d_in[7];
    const float* W_fdoc   = (const float*)d_in[8];
    const float* b_fdoc   = (const float*)d_in[9];
    const float* pos_emb  = (const float*)d_in[10];
    const float* w_content= (const float*)d_in[11];
    const float* W_sal    = (const float*)d_in[12];
    const float* W_nov    = (const float*)d_in[13];
    const float* w_abs    = (const float*)d_in[14];
    const float* bias     = (const float*)d_in[15];
    float* out = (float*)d_out;

    cudaFuncSetAttribute(k_mma_gemm, cudaFuncAttributeMaxDynamicSharedMemorySize, SMEM_BYTES);
    cudaFuncSetAttribute(k_mma_rec,  cudaFuncAttributeMaxDynamicSharedMemorySize, SMEM_REC);

    k_zero<<<1024, 256>>>();
    k_transpose<<<dim3(32, 32), dim3(32, 8)>>>(W_nov);

    // input projections, both dirs fused in one launch (grid.z = dir)
    dim3 gpre(GG/128, TB/128, 2);          // 16 x 128 x 2
    k_mma_gemm<<<gpre, 256, SMEM_BYTES>>>(emb, w_ih_f, w_ih_b, b_f, b_b, EE, 0);

    // recurrence: 64 steps, 256 blocks each, fused LSTM activation
    for (int s = 0; s < BB; s++) {
        dim3 grec(HH/16, TT/64, 2);        // 32 x 4 x 2
        k_mma_rec<<<grec, 128, SMEM_REC>>>(w_hh_f, w_hh_b, s & 1, s, 63 - s);
    }

    k_docmean<<<256, 256>>>();
    k_doc<<<8192, 256>>>(W_fdoc, b_fdoc);
    k_u<<<8192, 256>>>(W_sal, w_content);
    k_absp<<<1, 256>>>(pos_emb, w_abs);
    k_s0<<<2048, 256>>>(bias);

    // novelty GEMM
    dim3 gnn(H2/128, TB/128, 1);           // 8 x 128
    k_mma_gemm<<<gnn, 256, SMEM_BYTES>>>(nullptr, nullptr, nullptr, nullptr, nullptr, H2, 2);

    k_scan<<<BB, 256>>>(out);
}